// round 14
// baseline (speedup 1.0000x reference)
#include <cuda_runtime.h>
#include <cstdint>

// Fixed problem dims
#define BB 2
#define DD 160
#define HH 192
#define WW 160
#define CZ 40                 // z-chunk depth per block
#define NQ 40                 // WW/4 quads per row
#define BX (NQ * 2)           // 80: quad id = tx>>1, tensor select = tx&1
#define BY 4                  // rows per block
#define NTHREADS (BX * BY)    // 320
#define GY (HH / BY)          // 48
#define NCID (BB * DD / CZ)   // 8 z-chunks
#define NBLK (GY * NCID)      // 384
#define PLANE (HH * WW)
#define NVOX ((double)BB * DD * HH * WW)
#define FULL 0xffffffffu

// smem staging (double buffer)
#define RSTR 168              // floats per row slot (672B: 16B multiple, bank-skewed)
#define TSTR (6 * RSTR)       // tensor stride inside a buffer (1008 floats)
#define BSTR (2 * TSTR)       // buffer stride (2016 floats)
#define NCOPY 480             // 12 rows * 40 x-chunks of 16B
#define NP (CZ + 2)           // planes touched per chunk (42)

typedef unsigned long long u64;

__device__ float g_partial[NBLK];
__device__ unsigned int g_done = 0;

// ---------- packed f32x2 helpers (sm_100+) ----------
__device__ __forceinline__ u64 pack2(float lo, float hi) {
    u64 r; asm("mov.b64 %0, {%1,%2};" : "=l"(r) : "f"(lo), "f"(hi)); return r;
}
__device__ __forceinline__ void unpack2(u64 v, float& lo, float& hi) {
    asm("mov.b64 {%0,%1}, %2;" : "=f"(lo), "=f"(hi) : "l"(v));
}
__device__ __forceinline__ u64 fma2(u64 a, u64 b, u64 c) {
    u64 d; asm("fma.rn.f32x2 %0, %1, %2, %3;" : "=l"(d) : "l"(a), "l"(b), "l"(c)); return d;
}
__device__ __forceinline__ u64 add2(u64 a, u64 b) {
    u64 d; asm("add.rn.f32x2 %0, %1, %2;" : "=l"(d) : "l"(a), "l"(b)); return d;
}
__device__ __forceinline__ u64 sub2(u64 a, u64 b) {
    u64 d; asm("sub.rn.f32x2 %0, %1, %2;" : "=l"(d) : "l"(a), "l"(b)); return d;
}
__device__ __forceinline__ float fsqrt_approx(float x) {
    float r; asm("sqrt.approx.f32 %0, %1;" : "=f"(r) : "f"(x)); return r;
}

struct ABCp { u64 aA, aB, bA, bB, cA, cB; };   // a=sx*sy, b=dx*sy, c=sx*dy

// Load one plane's 12 rows (2 tensors x 6 y-rows) into registers (1.5 chunks/thread).
__device__ __forceinline__ void ldg_plane(float4* r,
                                          const float* __restrict__ pred,
                                          const float* __restrict__ targ,
                                          size_t batchOff, int z, int ybase, int tid) {
    const bool zv = (z >= 0) && (z < DD);
    #pragma unroll
    for (int pass = 0; pass < 2; ++pass) {
        const int idx = tid + pass * NTHREADS;
        r[pass] = make_float4(0.f, 0.f, 0.f, 0.f);
        if (idx < NCOPY) {
            const int rw = idx / 40;         // 0..11
            const int c  = idx % 40;         // 16B chunk within row
            const int tn = rw / 6;           // 0 = pred, 1 = targ
            const int ry = rw % 6;
            const int yrow = ybase - 1 + ry;
            if (zv && yrow >= 0 && yrow < HH) {
                const float* base = tn ? targ : pred;
                r[pass] = *reinterpret_cast<const float4*>(
                    base + batchOff + ((size_t)z * HH + yrow) * WW + c * 4);
            }
        }
    }
}

// Store staged registers into smem buffer bufI.
__device__ __forceinline__ void sts_plane(float* __restrict__ sbuf, int bufI,
                                          const float4* r, int tid) {
    float* bb = sbuf + bufI * BSTR;
    #pragma unroll
    for (int pass = 0; pass < 2; ++pass) {
        const int idx = tid + pass * NTHREADS;
        if (idx < NCOPY) {
            const int rw = idx / 40;
            const int c  = idx % 40;
            const int tn = rw / 6;
            const int ry = rw % 6;
            *reinterpret_cast<float4*>(bb + tn * TSTR + ry * RSTR + c * 4) = r[pass];
        }
    }
}

// Compute packed per-lane partials for one plane from smem.
// tbase points at this thread's tensor region; rows ty..ty+2 = y-1, y, y+1.
__device__ __forceinline__ ABCp plane_abc(const float* __restrict__ tbase,
                                          int ty, int x0, bool hasM, bool hasP,
                                          u64 TWO2) {
    const float* r0 = tbase + ty * RSTR;
    const float* r1 = r0 + RSTR;
    const float* r2 = r1 + RSTR;

    ulonglong2 q0 = *reinterpret_cast<const ulonglong2*>(r0 + x0);
    ulonglong2 q1 = *reinterpret_cast<const ulonglong2*>(r1 + x0);
    ulonglong2 q2 = *reinterpret_cast<const ulonglong2*>(r2 + x0);

    float em0 = hasM ? r0[x0 - 1] : 0.f;
    float em1 = hasM ? r1[x0 - 1] : 0.f;
    float em2 = hasM ? r2[x0 - 1] : 0.f;
    float ep0 = hasP ? r0[x0 + 4] : 0.f;
    float ep1 = hasP ? r1[x0 + 4] : 0.f;
    float ep2 = hasP ? r2[x0 + 4] : 0.f;

    // y-stage
    u64 sA = add2(fma2(TWO2, q1.x, q0.x), q2.x);
    u64 sB = add2(fma2(TWO2, q1.y, q0.y), q2.y);
    u64 dA = sub2(q2.x, q0.x);
    u64 dB = sub2(q2.y, q0.y);
    float sm = fmaf(2.f, em1, em0) + em2;
    float dm = em2 - em0;
    float sp = fmaf(2.f, ep1, ep0) + ep2;
    float dp = ep2 - ep0;

    float s0, s1, s2, s3, d0, d1, d2, d3;
    unpack2(sA, s0, s1); unpack2(sB, s2, s3);
    unpack2(dA, d0, d1); unpack2(dB, d2, d3);

    // x-stage on shifted packets
    u64 sL = pack2(sm, s0), sM = pack2(s1, s2), sR = pack2(s3, sp);
    u64 dL = pack2(dm, d0), dM = pack2(d1, d2), dR = pack2(d3, dp);
    ABCp o;
    o.aA = add2(fma2(TWO2, sA, sL), sM);
    o.aB = add2(fma2(TWO2, sB, sM), sR);
    o.bA = sub2(sM, sL);
    o.bB = sub2(sR, sM);
    o.cA = add2(fma2(TWO2, dA, dL), dM);
    o.cB = add2(fma2(TWO2, dB, dM), dR);
    return o;
}

// z-combine + magnitude, exchange with partner lane; BOTH lanes accumulate
// (total is 2x the true sum; final scale = 0.5/NVOX).
__device__ __forceinline__ float emit4(const ABCp& m2, const ABCp& m1, const ABCp& c,
                                       u64 TWO2, u64 EPS2) {
    u64 gxA = add2(fma2(TWO2, m1.bA, m2.bA), c.bA);
    u64 gxB = add2(fma2(TWO2, m1.bB, m2.bB), c.bB);
    u64 gyA = add2(fma2(TWO2, m1.cA, m2.cA), c.cA);
    u64 gyB = add2(fma2(TWO2, m1.cB, m2.cB), c.cB);
    u64 gzA = sub2(c.aA, m2.aA);
    u64 gzB = sub2(c.aB, m2.aB);
    u64 ssA = fma2(gxA, gxA, fma2(gyA, gyA, fma2(gzA, gzA, EPS2)));
    u64 ssB = fma2(gxB, gxB, fma2(gyB, gyB, fma2(gzB, gzB, EPS2)));
    float u0, u1, u2, u3;
    unpack2(ssA, u0, u1); unpack2(ssB, u2, u3);
    float g0 = fsqrt_approx(u0);
    float g1 = fsqrt_approx(u1);
    float g2 = fsqrt_approx(u2);
    float g3 = fsqrt_approx(u3);
    float o0 = __shfl_xor_sync(FULL, g0, 1);
    float o1 = __shfl_xor_sync(FULL, g1, 1);
    float o2 = __shfl_xor_sync(FULL, g2, 1);
    float o3 = __shfl_xor_sync(FULL, g3, 1);
    return fabsf(g0 - o0) + fabsf(g1 - o1) + fabsf(g2 - o2) + fabsf(g3 - o3);
}

__global__ __launch_bounds__(NTHREADS, 3)
void sobel_loss_fused(const float* __restrict__ pred, const float* __restrict__ targ,
                      float* __restrict__ out) {
    __shared__ float sbuf[2 * BSTR];           // 16128 B double buffer
    __shared__ float wsum[NTHREADS / 32];
    __shared__ int lastFlag;

    const int tx   = threadIdx.x;
    const int ty   = threadIdx.y;
    const int quad = tx >> 1;
    const int sel  = tx & 1;                  // 0 = pred, 1 = target
    const int x0   = quad * 4;
    const bool hasM = (quad > 0);
    const bool hasP = (quad < NQ - 1);
    const int tid  = ty * BX + tx;
    const int wid  = tid >> 5;
    const int lane = tid & 31;

    const u64 TWO2 = pack2(2.f, 2.f);
    const u64 EPS2 = pack2(1e-8f, 1e-8f);

    const int cid    = blockIdx.z;             // 0..7
    const int b      = cid >> 2;
    const int zstart = (cid & 3) * CZ;
    const int ybase  = blockIdx.y * BY;
    const size_t batchOff = (size_t)b * DD * PLANE;

    const float* tbase0 = sbuf + sel * TSTR;

    float4 ld[2];
    // prologue: stage plane 0 (z = zstart-1) into buf0
    ldg_plane(ld, pred, targ, batchOff, zstart - 1, ybase, tid);
    sts_plane(sbuf, 0, ld, tid);
    __syncthreads();

    float acc = 0.f;
    ABCp m2, m1;

    #pragma unroll 1
    for (int j = 0; j < NP; ++j) {
        // issue global loads for plane j+1 early (latency hidden by compute)
        if (j + 1 < NP)
            ldg_plane(ld, pred, targ, batchOff, zstart + j, ybase, tid);

        // compute plane j from buf[j&1]
        const float* tb = tbase0 + (j & 1) * BSTR;
        ABCp c = plane_abc(tb, ty, x0, hasM, hasP, TWO2);
        if (j >= 2)
            acc += emit4(m2, m1, c, TWO2, EPS2);
        m2 = m1; m1 = c;

        // stage plane j+1 into the other buffer, then one barrier
        if (j + 1 < NP)
            sts_plane(sbuf, (j + 1) & 1, ld, tid);
        __syncthreads();
    }

    // ---------- block reduction (deterministic) ----------
    float v = acc;
    #pragma unroll
    for (int o = 16; o > 0; o >>= 1)
        v += __shfl_down_sync(FULL, v, o);
    if (lane == 0) wsum[wid] = v;
    __syncthreads();

    if (tid == 0) {
        float s = 0.f;
        #pragma unroll
        for (int w = 0; w < NTHREADS / 32; ++w) s += wsum[w];
        g_partial[blockIdx.z * GY + blockIdx.y] = s;
        __threadfence();
        unsigned d = atomicAdd(&g_done, 1u);
        lastFlag = (d == NBLK - 1);
    }
    __syncthreads();

    // ---------- last block folds all partials (fixed order -> deterministic) ----------
    if (lastFlag) {
        const volatile float* gp = g_partial;
        float s = 0.f;
        for (int i = tid; i < NBLK; i += NTHREADS)
            s += gp[i];
        #pragma unroll
        for (int o = 16; o > 0; o >>= 1)
            s += __shfl_down_sync(FULL, s, o);
        if (lane == 0) wsum[wid] = s;
        __syncthreads();
        if (tid == 0) {
            float tot = 0.f;
            #pragma unroll
            for (int w = 0; w < NTHREADS / 32; ++w) tot += wsum[w];
            out[0] = tot * (float)(0.5 / NVOX);   // 0.5: both lanes accumulated
            g_done = 0;    // reset for next graph replay
        }
    }
}

extern "C" void kernel_launch(void* const* d_in, const int* in_sizes, int n_in,
                              void* d_out, int out_size) {
    const float* pred = (const float*)d_in[0];
    const float* targ = (const float*)d_in[1];
    dim3 blk(BX, BY, 1);
    dim3 grd(1, GY, NCID);
    sobel_loss_fused<<<grd, blk>>>(pred, targ, (float*)d_out);
}

// round 15
// speedup vs baseline: 1.6232x; 1.6232x over previous
#include <cuda_runtime.h>
#include <cstdint>

// Fixed problem dims
#define BB 2
#define DD 160
#define HH 192
#define WW 160
#define CZ 40                 // z-chunk depth per block
#define NQ 40                 // WW/4 quads per row
#define BX (NQ * 2)           // 80: quad id = tx>>1, tensor select = tx&1
#define BY 4                  // rows per block
#define NTHREADS (BX * BY)    // 320
#define GY (HH / BY)          // 48
#define NCID (BB * DD / CZ)   // 8 z-chunks
#define NBLK (GY * NCID)      // 384
#define PLANE (HH * WW)
#define NVOX ((double)BB * DD * HH * WW)
#define FULL 0xffffffffu

typedef unsigned long long u64;

__device__ float g_partial[NBLK];
__device__ unsigned int g_done = 0;

// ---------- packed f32x2 helpers (sm_100+) ----------
__device__ __forceinline__ u64 pack2(float lo, float hi) {
    u64 r; asm("mov.b64 %0, {%1,%2};" : "=l"(r) : "f"(lo), "f"(hi)); return r;
}
__device__ __forceinline__ void unpack2(u64 v, float& lo, float& hi) {
    asm("mov.b64 {%0,%1}, %2;" : "=f"(lo), "=f"(hi) : "l"(v));
}
__device__ __forceinline__ u64 fma2(u64 a, u64 b, u64 c) {
    u64 d; asm("fma.rn.f32x2 %0, %1, %2, %3;" : "=l"(d) : "l"(a), "l"(b), "l"(c)); return d;
}
__device__ __forceinline__ u64 add2(u64 a, u64 b) {
    u64 d; asm("add.rn.f32x2 %0, %1, %2;" : "=l"(d) : "l"(a), "l"(b)); return d;
}
__device__ __forceinline__ u64 sub2(u64 a, u64 b) {
    u64 d; asm("sub.rn.f32x2 %0, %1, %2;" : "=l"(d) : "l"(a), "l"(b)); return d;
}
__device__ __forceinline__ float fsqrt_approx(float x) {
    float r; asm("sqrt.approx.f32 %0, %1;" : "=f"(r) : "f"(x)); return r;
}
__device__ __forceinline__ void prefetchL1(const float* p) {
    asm volatile("prefetch.global.L1 [%0];" :: "l"(p));
}

struct ABCp { u64 aA, aB, bA, bB, cA, cB; };   // a=sx*sy, b=dx*sy, c=sx*dy

struct Ctx {
    bool lftShfl, rgtShfl;   // x-halo available from lane +-2 via shuffle
    bool hasM, hasP;         // global x-boundary flags
};

// Build packed per-lane partials for one plane. p points at (y, x0) of plane z.
// v0/v1/v2 = validity of rows y-1 / y / y+1 (z and y bounds folded in).
__device__ __forceinline__ ABCp plane_abc(const float* __restrict__ p,
                                          bool v0, bool v1, bool v2,
                                          const Ctx cx, u64 TWO2) {
    u64 r0A = 0, r0B = 0, r1A = 0, r1B = 0, r2A = 0, r2B = 0;
    if (v0) { ulonglong2 q = __ldg(reinterpret_cast<const ulonglong2*>(p - WW)); r0A = q.x; r0B = q.y; }
    if (v1) { ulonglong2 q = __ldg(reinterpret_cast<const ulonglong2*>(p));      r1A = q.x; r1B = q.y; }
    if (v2) { ulonglong2 q = __ldg(reinterpret_cast<const ulonglong2*>(p + WW)); r2A = q.x; r2B = q.y; }

    // y-stage (elementwise on own quad)
    u64 sA = add2(fma2(TWO2, r1A, r0A), r2A);
    u64 sB = add2(fma2(TWO2, r1B, r0B), r2B);
    u64 dA = sub2(r2A, r0A);
    u64 dB = sub2(r2B, r0B);

    float s0, s1, s2, s3, d0, d1, d2, d3;
    unpack2(sA, s0, s1); unpack2(sB, s2, s3);
    unpack2(dA, d0, d1); unpack2(dB, d2, d3);

    // x-halo from neighbor lanes (same tensor = lane +- 2)
    float sm = __shfl_up_sync  (FULL, s3, 2);
    float dm = __shfl_up_sync  (FULL, d3, 2);
    float sp = __shfl_down_sync(FULL, s0, 2);
    float dp = __shfl_down_sync(FULL, d0, 2);

    // fallback for lanes whose neighbor is outside the warp / volume
    if (!cx.lftShfl) {
        float a = 0.f, b = 0.f, c = 0.f;
        if (cx.hasM) {
            if (v0) a = __ldg(p - WW - 1);
            if (v1) b = __ldg(p - 1);
            if (v2) c = __ldg(p + WW - 1);
        }
        sm = fmaf(2.f, b, a) + c;
        dm = c - a;
    }
    if (!cx.rgtShfl) {
        float a = 0.f, b = 0.f, c = 0.f;
        if (cx.hasP) {
            if (v0) a = __ldg(p - WW + 4);
            if (v1) b = __ldg(p + 4);
            if (v2) c = __ldg(p + WW + 4);
        }
        sp = fmaf(2.f, b, a) + c;
        dp = c - a;
    }

    // x-stage on shifted packets
    u64 sL = pack2(sm, s0), sM = pack2(s1, s2), sR = pack2(s3, sp);
    u64 dL = pack2(dm, d0), dM = pack2(d1, d2), dR = pack2(d3, dp);
    ABCp o;
    o.aA = add2(fma2(TWO2, sA, sL), sM);
    o.aB = add2(fma2(TWO2, sB, sM), sR);
    o.bA = sub2(sM, sL);
    o.bB = sub2(sR, sM);
    o.cA = add2(fma2(TWO2, dA, dL), dM);
    o.cB = add2(fma2(TWO2, dB, dM), dR);
    return o;
}

// z-combine + magnitude, exchange with partner lane; BOTH lanes accumulate
// (total is 2x the true sum; final scale = 0.5/NVOX).
__device__ __forceinline__ float emit4(const ABCp& m2, const ABCp& m1, const ABCp& c,
                                       u64 TWO2, u64 EPS2) {
    u64 gxA = add2(fma2(TWO2, m1.bA, m2.bA), c.bA);
    u64 gxB = add2(fma2(TWO2, m1.bB, m2.bB), c.bB);
    u64 gyA = add2(fma2(TWO2, m1.cA, m2.cA), c.cA);
    u64 gyB = add2(fma2(TWO2, m1.cB, m2.cB), c.cB);
    u64 gzA = sub2(c.aA, m2.aA);
    u64 gzB = sub2(c.aB, m2.aB);
    u64 ssA = fma2(gxA, gxA, fma2(gyA, gyA, fma2(gzA, gzA, EPS2)));
    u64 ssB = fma2(gxB, gxB, fma2(gyB, gyB, fma2(gzB, gzB, EPS2)));
    float u0, u1, u2, u3;
    unpack2(ssA, u0, u1); unpack2(ssB, u2, u3);
    float g0 = fsqrt_approx(u0);
    float g1 = fsqrt_approx(u1);
    float g2 = fsqrt_approx(u2);
    float g3 = fsqrt_approx(u3);
    float o0 = __shfl_xor_sync(FULL, g0, 1);
    float o1 = __shfl_xor_sync(FULL, g1, 1);
    float o2 = __shfl_xor_sync(FULL, g2, 1);
    float o3 = __shfl_xor_sync(FULL, g3, 1);
    return fabsf(g0 - o0) + fabsf(g1 - o1) + fabsf(g2 - o2) + fabsf(g3 - o3);
}

__global__ __launch_bounds__(NTHREADS, 3)
void sobel_loss_fused(const float* __restrict__ pred, const float* __restrict__ targ,
                      float* __restrict__ out) {
    const int tx   = threadIdx.x;
    const int ty   = threadIdx.y;
    const int quad = tx >> 1;
    const int sel  = tx & 1;                  // 0 = pred, 1 = target
    const int x0   = quad * 4;
    const int y    = blockIdx.y * BY + ty;
    const bool y0ok = (y > 0);
    const bool y2ok = (y < HH - 1);

    const float* __restrict__ src = sel ? targ : pred;

    const u64 TWO2 = pack2(2.f, 2.f);
    const u64 EPS2 = pack2(1e-8f, 1e-8f);

    // x-halo routing: is lane+-2 the same-row neighbor quad?
    Ctx cx;
    {
        const int key = (ty << 8) | quad;
        const int kUp = __shfl_up_sync  (FULL, key, 2);
        const int kDn = __shfl_down_sync(FULL, key, 2);
        cx.hasM = (quad > 0);
        cx.hasP = (quad < NQ - 1);
        cx.lftShfl = cx.hasM && (kUp == key - 1);
        cx.rgtShfl = cx.hasP && (kDn == key + 1);
    }

    const int cid    = blockIdx.z;             // 0..7
    const int b      = cid >> 2;
    const int zstart = (cid & 3) * CZ;
    // prefetch past-end guard: only the last chunk of batch 1 can run past the
    // allocation (batch 0's overflow lands in batch 1 = valid memory).
    const bool pfOK  = (cid != NCID - 1);

    const float* Pp = src + (size_t)b * DD * PLANE
                      + (ptrdiff_t)((zstart - 1) * HH + y) * WW + x0;

    float acc = 0.f;
    ABCp m2, m1;
    // warmup plane z = zstart-1 (may be out of volume)
    {
        const bool zv = (zstart > 0);
        m2 = plane_abc(Pp, zv && y0ok, zv, zv && y2ok, cx, TWO2);
        prefetchL1(Pp + PLANE);
        Pp += PLANE;
    }
    // warmup plane z = zstart (always in volume)
    {
        m1 = plane_abc(Pp, y0ok, true, y2ok, cx, TWO2);
        prefetchL1(Pp + PLANE);
        Pp += PLANE;
    }
    // interior planes: z = zstart+1 .. zstart+CZ-1 (always valid); 39 iters = 13x3
    #pragma unroll 3
    for (int j = 0; j < CZ - 1; ++j) {
        ABCp c = plane_abc(Pp, y0ok, true, y2ok, cx, TWO2);
        if (j != CZ - 2 || pfOK)
            prefetchL1(Pp + PLANE);            // center row of next plane
        acc += emit4(m2, m1, c, TWO2, EPS2);
        m2 = m1; m1 = c;
        Pp += PLANE;
    }
    // final plane z = zstart+CZ (may be out of volume); emits z = zstart+CZ-1
    {
        const bool zv = (zstart + CZ < DD);
        ABCp c = plane_abc(Pp, zv && y0ok, zv, zv && y2ok, cx, TWO2);
        acc += emit4(m2, m1, c, TWO2, EPS2);
    }

    // ---------- block reduction (deterministic) ----------
    __shared__ float wsum[NTHREADS / 32];
    __shared__ int lastFlag;
    const int tid  = ty * BX + tx;
    const int wid  = tid >> 5;
    const int lane = tid & 31;

    float v = acc;
    #pragma unroll
    for (int o = 16; o > 0; o >>= 1)
        v += __shfl_down_sync(FULL, v, o);
    if (lane == 0) wsum[wid] = v;
    __syncthreads();

    if (tid == 0) {
        float s = 0.f;
        #pragma unroll
        for (int w = 0; w < NTHREADS / 32; ++w) s += wsum[w];
        g_partial[blockIdx.z * GY + blockIdx.y] = s;
        __threadfence();
        unsigned d = atomicAdd(&g_done, 1u);
        lastFlag = (d == NBLK - 1);
    }
    __syncthreads();

    // ---------- last block folds all partials (fixed order -> deterministic) ----------
    if (lastFlag) {
        const volatile float* gp = g_partial;
        float s = 0.f;
        for (int i = tid; i < NBLK; i += NTHREADS)
            s += gp[i];
        #pragma unroll
        for (int o = 16; o > 0; o >>= 1)
            s += __shfl_down_sync(FULL, s, o);
        if (lane == 0) wsum[wid] = s;
        __syncthreads();
        if (tid == 0) {
            float tot = 0.f;
            #pragma unroll
            for (int w = 0; w < NTHREADS / 32; ++w) tot += wsum[w];
            out[0] = tot * (float)(0.5 / NVOX);   // 0.5: both lanes accumulated
            g_done = 0;    // reset for next graph replay
        }
    }
}

extern "C" void kernel_launch(void* const* d_in, const int* in_sizes, int n_in,
                              void* d_out, int out_size) {
    const float* pred = (const float*)d_in[0];
    const float* targ = (const float*)d_in[1];
    dim3 blk(BX, BY, 1);
    dim3 grd(1, GY, NCID);
    sobel_loss_fused<<<grd, blk>>>(pred, targ, (float*)d_out);
}

// round 16
// speedup vs baseline: 1.6675x; 1.0272x over previous
#include <cuda_runtime.h>
#include <cstdint>

// Fixed problem dims
#define BB 2
#define DD 160
#define HH 192
#define WW 160
#define CZ 40                 // z-chunk depth per block
#define NQ 40                 // WW/4 quads per row
#define BX (NQ * 2)           // 80: quad id = tx>>1, tensor select = tx&1
#define BY 4                  // rows per block
#define NTHREADS (BX * BY)    // 320
#define GY (HH / BY)          // 48
#define NCID (BB * DD / CZ)   // 8 z-chunks
#define NBLK (GY * NCID)      // 384
#define PLANE (HH * WW)
#define NVOX ((double)BB * DD * HH * WW)
#define FULL 0xffffffffu

typedef unsigned long long u64;

__device__ float g_partial[NBLK];
__device__ unsigned int g_done = 0;

// ---------- packed f32x2 helpers (sm_100+) ----------
__device__ __forceinline__ u64 pack2(float lo, float hi) {
    u64 r; asm("mov.b64 %0, {%1,%2};" : "=l"(r) : "f"(lo), "f"(hi)); return r;
}
__device__ __forceinline__ void unpack2(u64 v, float& lo, float& hi) {
    asm("mov.b64 {%0,%1}, %2;" : "=f"(lo), "=f"(hi) : "l"(v));
}
__device__ __forceinline__ u64 fma2(u64 a, u64 b, u64 c) {
    u64 d; asm("fma.rn.f32x2 %0, %1, %2, %3;" : "=l"(d) : "l"(a), "l"(b), "l"(c)); return d;
}
__device__ __forceinline__ u64 add2(u64 a, u64 b) {
    u64 d; asm("add.rn.f32x2 %0, %1, %2;" : "=l"(d) : "l"(a), "l"(b)); return d;
}
__device__ __forceinline__ u64 sub2(u64 a, u64 b) {
    u64 d; asm("sub.rn.f32x2 %0, %1, %2;" : "=l"(d) : "l"(a), "l"(b)); return d;
}
__device__ __forceinline__ float fsqrt_approx(float x) {
    float r; asm("sqrt.approx.f32 %0, %1;" : "=f"(r) : "f"(x)); return r;
}

struct ABCp { u64 aA, aB, bA, bB, cA, cB; };   // a=sx*sy, b=dx*sy, c=sx*dy

struct Ctx {
    bool lftShfl, rgtShfl;   // x-halo available from lane +-2 via shuffle
    bool hasM, hasP;         // global x-boundary flags
};

// Build packed per-lane partials for one plane. p points at (y, x0) of plane z.
// v0/v1/v2 = validity of rows y-1 / y / y+1 (z and y bounds folded in).
__device__ __forceinline__ ABCp plane_abc(const float* __restrict__ p,
                                          bool v0, bool v1, bool v2,
                                          const Ctx cx, u64 TWO2) {
    u64 r0A = 0, r0B = 0, r1A = 0, r1B = 0, r2A = 0, r2B = 0;
    if (v0) { ulonglong2 q = __ldg(reinterpret_cast<const ulonglong2*>(p - WW)); r0A = q.x; r0B = q.y; }
    if (v1) { ulonglong2 q = __ldg(reinterpret_cast<const ulonglong2*>(p));      r1A = q.x; r1B = q.y; }
    if (v2) { ulonglong2 q = __ldg(reinterpret_cast<const ulonglong2*>(p + WW)); r2A = q.x; r2B = q.y; }

    // y-stage (elementwise on own quad)
    u64 sA = add2(fma2(TWO2, r1A, r0A), r2A);
    u64 sB = add2(fma2(TWO2, r1B, r0B), r2B);
    u64 dA = sub2(r2A, r0A);
    u64 dB = sub2(r2B, r0B);

    float s0, s1, s2, s3, d0, d1, d2, d3;
    unpack2(sA, s0, s1); unpack2(sB, s2, s3);
    unpack2(dA, d0, d1); unpack2(dB, d2, d3);

    // x-halo from neighbor lanes (same tensor = lane +- 2)
    float sm = __shfl_up_sync  (FULL, s3, 2);
    float dm = __shfl_up_sync  (FULL, d3, 2);
    float sp = __shfl_down_sync(FULL, s0, 2);
    float dp = __shfl_down_sync(FULL, d0, 2);

    // fallback for lanes whose neighbor is outside the warp / volume
    if (!cx.lftShfl) {
        float a = 0.f, b = 0.f, c = 0.f;
        if (cx.hasM) {
            if (v0) a = __ldg(p - WW - 1);
            if (v1) b = __ldg(p - 1);
            if (v2) c = __ldg(p + WW - 1);
        }
        sm = fmaf(2.f, b, a) + c;
        dm = c - a;
    }
    if (!cx.rgtShfl) {
        float a = 0.f, b = 0.f, c = 0.f;
        if (cx.hasP) {
            if (v0) a = __ldg(p - WW + 4);
            if (v1) b = __ldg(p + 4);
            if (v2) c = __ldg(p + WW + 4);
        }
        sp = fmaf(2.f, b, a) + c;
        dp = c - a;
    }

    // x-stage on shifted packets
    u64 sL = pack2(sm, s0), sM = pack2(s1, s2), sR = pack2(s3, sp);
    u64 dL = pack2(dm, d0), dM = pack2(d1, d2), dR = pack2(d3, dp);
    ABCp o;
    o.aA = add2(fma2(TWO2, sA, sL), sM);
    o.aB = add2(fma2(TWO2, sB, sM), sR);
    o.bA = sub2(sM, sL);
    o.bB = sub2(sR, sM);
    o.cA = add2(fma2(TWO2, dA, dL), dM);
    o.cB = add2(fma2(TWO2, dB, dM), dR);
    return o;
}

// z-combine + magnitude, exchange with partner lane; BOTH lanes accumulate
// (total is 2x the true sum; final scale = 0.5/NVOX).
__device__ __forceinline__ float emit4(const ABCp& m2, const ABCp& m1, const ABCp& c,
                                       u64 TWO2, u64 EPS2) {
    u64 gxA = add2(fma2(TWO2, m1.bA, m2.bA), c.bA);
    u64 gxB = add2(fma2(TWO2, m1.bB, m2.bB), c.bB);
    u64 gyA = add2(fma2(TWO2, m1.cA, m2.cA), c.cA);
    u64 gyB = add2(fma2(TWO2, m1.cB, m2.cB), c.cB);
    u64 gzA = sub2(c.aA, m2.aA);
    u64 gzB = sub2(c.aB, m2.aB);
    u64 ssA = fma2(gxA, gxA, fma2(gyA, gyA, fma2(gzA, gzA, EPS2)));
    u64 ssB = fma2(gxB, gxB, fma2(gyB, gyB, fma2(gzB, gzB, EPS2)));
    float u0, u1, u2, u3;
    unpack2(ssA, u0, u1); unpack2(ssB, u2, u3);
    float g0 = fsqrt_approx(u0);
    float g1 = fsqrt_approx(u1);
    float g2 = fsqrt_approx(u2);
    float g3 = fsqrt_approx(u3);
    float o0 = __shfl_xor_sync(FULL, g0, 1);
    float o1 = __shfl_xor_sync(FULL, g1, 1);
    float o2 = __shfl_xor_sync(FULL, g2, 1);
    float o3 = __shfl_xor_sync(FULL, g3, 1);
    return fabsf(g0 - o0) + fabsf(g1 - o1) + fabsf(g2 - o2) + fabsf(g3 - o3);
}

__global__ __launch_bounds__(NTHREADS, 3)
void sobel_loss_fused(const float* __restrict__ pred, const float* __restrict__ targ,
                      float* __restrict__ out) {
    const int tx   = threadIdx.x;
    const int ty   = threadIdx.y;
    const int quad = tx >> 1;
    const int sel  = tx & 1;                  // 0 = pred, 1 = target
    const int x0   = quad * 4;
    const int y    = blockIdx.y * BY + ty;
    const bool y0ok = (y > 0);
    const bool y2ok = (y < HH - 1);

    const float* __restrict__ src = sel ? targ : pred;

    const u64 TWO2 = pack2(2.f, 2.f);
    const u64 EPS2 = pack2(1e-8f, 1e-8f);

    // x-halo routing: is lane+-2 the same-row neighbor quad?
    Ctx cx;
    {
        const int key = (ty << 8) | quad;
        const int kUp = __shfl_up_sync  (FULL, key, 2);
        const int kDn = __shfl_down_sync(FULL, key, 2);
        cx.hasM = (quad > 0);
        cx.hasP = (quad < NQ - 1);
        cx.lftShfl = cx.hasM && (kUp == key - 1);
        cx.rgtShfl = cx.hasP && (kDn == key + 1);
    }

    const int cid    = blockIdx.z;             // 0..7
    const int b      = cid >> 2;
    const int zstart = (cid & 3) * CZ;

    const float* Pp = src + (size_t)b * DD * PLANE
                      + (ptrdiff_t)((zstart - 1) * HH + y) * WW + x0;

    float acc = 0.f;
    ABCp m2, m1;
    // warmup plane z = zstart-1 (may be out of volume)
    {
        const bool zv = (zstart > 0);
        m2 = plane_abc(Pp, zv && y0ok, zv, zv && y2ok, cx, TWO2);
        Pp += PLANE;
    }
    // warmup plane z = zstart (always in volume)
    {
        m1 = plane_abc(Pp, y0ok, true, y2ok, cx, TWO2);
        Pp += PLANE;
    }
    // interior planes: z = zstart+1 .. zstart+CZ-1 (always valid); 39 iters = 13x3
    #pragma unroll 3
    for (int j = 0; j < CZ - 1; ++j) {
        ABCp c = plane_abc(Pp, y0ok, true, y2ok, cx, TWO2);
        acc += emit4(m2, m1, c, TWO2, EPS2);
        m2 = m1; m1 = c;
        Pp += PLANE;
    }
    // final plane z = zstart+CZ (may be out of volume); emits z = zstart+CZ-1
    {
        const bool zv = (zstart + CZ < DD);
        ABCp c = plane_abc(Pp, zv && y0ok, zv, zv && y2ok, cx, TWO2);
        acc += emit4(m2, m1, c, TWO2, EPS2);
    }

    // ---------- block reduction (deterministic) ----------
    __shared__ float wsum[NTHREADS / 32];
    __shared__ int lastFlag;
    const int tid  = ty * BX + tx;
    const int wid  = tid >> 5;
    const int lane = tid & 31;

    float v = acc;
    #pragma unroll
    for (int o = 16; o > 0; o >>= 1)
        v += __shfl_down_sync(FULL, v, o);
    if (lane == 0) wsum[wid] = v;
    __syncthreads();

    if (tid == 0) {
        float s = 0.f;
        #pragma unroll
        for (int w = 0; w < NTHREADS / 32; ++w) s += wsum[w];
        g_partial[blockIdx.z * GY + blockIdx.y] = s;
        __threadfence();
        unsigned d = atomicAdd(&g_done, 1u);
        lastFlag = (d == NBLK - 1);
    }
    __syncthreads();

    // ---------- last block folds all partials (fixed order -> deterministic) ----------
    if (lastFlag) {
        const volatile float* gp = g_partial;
        float s = 0.f;
        for (int i = tid; i < NBLK; i += NTHREADS)
            s += gp[i];
        #pragma unroll
        for (int o = 16; o > 0; o >>= 1)
            s += __shfl_down_sync(FULL, s, o);
        if (lane == 0) wsum[wid] = s;
        __syncthreads();
        if (tid == 0) {
            float tot = 0.f;
            #pragma unroll
            for (int w = 0; w < NTHREADS / 32; ++w) tot += wsum[w];
            out[0] = tot * (float)(0.5 / NVOX);   // 0.5: both lanes accumulated
            g_done = 0;    // reset for next graph replay
        }
    }
}

extern "C" void kernel_launch(void* const* d_in, const int* in_sizes, int n_in,
                              void* d_out, int out_size) {
    const float* pred = (const float*)d_in[0];
    const float* targ = (const float*)d_in[1];
    dim3 blk(BX, BY, 1);
    dim3 grd(1, GY, NCID);
    sobel_loss_fused<<<grd, blk>>>(pred, targ, (float*)d_out);
}

// round 17
// speedup vs baseline: 1.6782x; 1.0065x over previous
#include <cuda_runtime.h>
#include <cstdint>

// Fixed problem dims
#define BB 2
#define DD 160
#define HH 192
#define WW 160
#define CZ 40                 // z-chunk depth per block
#define NQ 40                 // WW/4 quads per row
#define BX (NQ * 2)           // 80: quad id = tx>>1, tensor select = tx&1
#define BY 6                  // rows per block (halo ratio 8/6 = 1.33)
#define NTHREADS (BX * BY)    // 480
#define GY (HH / BY)          // 32
#define NCID (BB * DD / CZ)   // 8 z-chunks
#define NBLK (GY * NCID)      // 256
#define PLANE (HH * WW)
#define NVOX ((double)BB * DD * HH * WW)
#define FULL 0xffffffffu

typedef unsigned long long u64;

__device__ float g_partial[NBLK];
__device__ unsigned int g_done = 0;

// ---------- packed f32x2 helpers (sm_100+) ----------
__device__ __forceinline__ u64 pack2(float lo, float hi) {
    u64 r; asm("mov.b64 %0, {%1,%2};" : "=l"(r) : "f"(lo), "f"(hi)); return r;
}
__device__ __forceinline__ void unpack2(u64 v, float& lo, float& hi) {
    asm("mov.b64 {%0,%1}, %2;" : "=f"(lo), "=f"(hi) : "l"(v));
}
__device__ __forceinline__ u64 fma2(u64 a, u64 b, u64 c) {
    u64 d; asm("fma.rn.f32x2 %0, %1, %2, %3;" : "=l"(d) : "l"(a), "l"(b), "l"(c)); return d;
}
__device__ __forceinline__ u64 add2(u64 a, u64 b) {
    u64 d; asm("add.rn.f32x2 %0, %1, %2;" : "=l"(d) : "l"(a), "l"(b)); return d;
}
__device__ __forceinline__ u64 sub2(u64 a, u64 b) {
    u64 d; asm("sub.rn.f32x2 %0, %1, %2;" : "=l"(d) : "l"(a), "l"(b)); return d;
}
__device__ __forceinline__ float fsqrt_approx(float x) {
    float r; asm("sqrt.approx.f32 %0, %1;" : "=f"(r) : "f"(x)); return r;
}

struct ABCp { u64 aA, aB, bA, bB, cA, cB; };   // a=sx*sy, b=dx*sy, c=sx*dy

struct Ctx {
    bool lftShfl, rgtShfl;   // x-halo available from lane +-2 via shuffle
    bool hasM, hasP;         // global x-boundary flags
};

// Build packed per-lane partials for one plane. p points at (y, x0) of plane z.
// v0/v1/v2 = validity of rows y-1 / y / y+1 (z and y bounds folded in).
__device__ __forceinline__ ABCp plane_abc(const float* __restrict__ p,
                                          bool v0, bool v1, bool v2,
                                          const Ctx cx, u64 TWO2) {
    u64 r0A = 0, r0B = 0, r1A = 0, r1B = 0, r2A = 0, r2B = 0;
    if (v0) { ulonglong2 q = __ldg(reinterpret_cast<const ulonglong2*>(p - WW)); r0A = q.x; r0B = q.y; }
    if (v1) { ulonglong2 q = __ldg(reinterpret_cast<const ulonglong2*>(p));      r1A = q.x; r1B = q.y; }
    if (v2) { ulonglong2 q = __ldg(reinterpret_cast<const ulonglong2*>(p + WW)); r2A = q.x; r2B = q.y; }

    // y-stage (elementwise on own quad)
    u64 sA = add2(fma2(TWO2, r1A, r0A), r2A);
    u64 sB = add2(fma2(TWO2, r1B, r0B), r2B);
    u64 dA = sub2(r2A, r0A);
    u64 dB = sub2(r2B, r0B);

    float s0, s1, s2, s3, d0, d1, d2, d3;
    unpack2(sA, s0, s1); unpack2(sB, s2, s3);
    unpack2(dA, d0, d1); unpack2(dB, d2, d3);

    // x-halo from neighbor lanes (same tensor = lane +- 2)
    float sm = __shfl_up_sync  (FULL, s3, 2);
    float dm = __shfl_up_sync  (FULL, d3, 2);
    float sp = __shfl_down_sync(FULL, s0, 2);
    float dp = __shfl_down_sync(FULL, d0, 2);

    // fallback for lanes whose neighbor is outside the warp / volume
    if (!cx.lftShfl) {
        float a = 0.f, b = 0.f, c = 0.f;
        if (cx.hasM) {
            if (v0) a = __ldg(p - WW - 1);
            if (v1) b = __ldg(p - 1);
            if (v2) c = __ldg(p + WW - 1);
        }
        sm = fmaf(2.f, b, a) + c;
        dm = c - a;
    }
    if (!cx.rgtShfl) {
        float a = 0.f, b = 0.f, c = 0.f;
        if (cx.hasP) {
            if (v0) a = __ldg(p - WW + 4);
            if (v1) b = __ldg(p + 4);
            if (v2) c = __ldg(p + WW + 4);
        }
        sp = fmaf(2.f, b, a) + c;
        dp = c - a;
    }

    // x-stage on shifted packets
    u64 sL = pack2(sm, s0), sM = pack2(s1, s2), sR = pack2(s3, sp);
    u64 dL = pack2(dm, d0), dM = pack2(d1, d2), dR = pack2(d3, dp);
    ABCp o;
    o.aA = add2(fma2(TWO2, sA, sL), sM);
    o.aB = add2(fma2(TWO2, sB, sM), sR);
    o.bA = sub2(sM, sL);
    o.bB = sub2(sR, sM);
    o.cA = add2(fma2(TWO2, dA, dL), dM);
    o.cB = add2(fma2(TWO2, dB, dM), dR);
    return o;
}

// z-combine + magnitude, exchange with partner lane; BOTH lanes accumulate
// (total is 2x the true sum; final scale = 0.5/NVOX).
__device__ __forceinline__ float emit4(const ABCp& m2, const ABCp& m1, const ABCp& c,
                                       u64 TWO2, u64 EPS2) {
    u64 gxA = add2(fma2(TWO2, m1.bA, m2.bA), c.bA);
    u64 gxB = add2(fma2(TWO2, m1.bB, m2.bB), c.bB);
    u64 gyA = add2(fma2(TWO2, m1.cA, m2.cA), c.cA);
    u64 gyB = add2(fma2(TWO2, m1.cB, m2.cB), c.cB);
    u64 gzA = sub2(c.aA, m2.aA);
    u64 gzB = sub2(c.aB, m2.aB);
    u64 ssA = fma2(gxA, gxA, fma2(gyA, gyA, fma2(gzA, gzA, EPS2)));
    u64 ssB = fma2(gxB, gxB, fma2(gyB, gyB, fma2(gzB, gzB, EPS2)));
    float u0, u1, u2, u3;
    unpack2(ssA, u0, u1); unpack2(ssB, u2, u3);
    float g0 = fsqrt_approx(u0);
    float g1 = fsqrt_approx(u1);
    float g2 = fsqrt_approx(u2);
    float g3 = fsqrt_approx(u3);
    float o0 = __shfl_xor_sync(FULL, g0, 1);
    float o1 = __shfl_xor_sync(FULL, g1, 1);
    float o2 = __shfl_xor_sync(FULL, g2, 1);
    float o3 = __shfl_xor_sync(FULL, g3, 1);
    return fabsf(g0 - o0) + fabsf(g1 - o1) + fabsf(g2 - o2) + fabsf(g3 - o3);
}

__global__ __launch_bounds__(NTHREADS, 2)
void sobel_loss_fused(const float* __restrict__ pred, const float* __restrict__ targ,
                      float* __restrict__ out) {
    const int tx   = threadIdx.x;
    const int ty   = threadIdx.y;
    const int quad = tx >> 1;
    const int sel  = tx & 1;                  // 0 = pred, 1 = target
    const int x0   = quad * 4;
    const int y    = blockIdx.y * BY + ty;
    const bool y0ok = (y > 0);
    const bool y2ok = (y < HH - 1);

    const float* __restrict__ src = sel ? targ : pred;

    const u64 TWO2 = pack2(2.f, 2.f);
    const u64 EPS2 = pack2(1e-8f, 1e-8f);

    // x-halo routing: is lane+-2 the same-row neighbor quad?
    Ctx cx;
    {
        const int key = (ty << 8) | quad;
        const int kUp = __shfl_up_sync  (FULL, key, 2);
        const int kDn = __shfl_down_sync(FULL, key, 2);
        cx.hasM = (quad > 0);
        cx.hasP = (quad < NQ - 1);
        cx.lftShfl = cx.hasM && (kUp == key - 1);
        cx.rgtShfl = cx.hasP && (kDn == key + 1);
    }

    const int cid    = blockIdx.z;             // 0..7
    const int b      = cid >> 2;
    const int zstart = (cid & 3) * CZ;

    const float* Pp = src + (size_t)b * DD * PLANE
                      + (ptrdiff_t)((zstart - 1) * HH + y) * WW + x0;

    float acc = 0.f;
    ABCp m2, m1;
    // warmup plane z = zstart-1 (may be out of volume)
    {
        const bool zv = (zstart > 0);
        m2 = plane_abc(Pp, zv && y0ok, zv, zv && y2ok, cx, TWO2);
        Pp += PLANE;
    }
    // warmup plane z = zstart (always in volume)
    {
        m1 = plane_abc(Pp, y0ok, true, y2ok, cx, TWO2);
        Pp += PLANE;
    }
    // interior planes: z = zstart+1 .. zstart+CZ-1 (always valid); 39 iters = 13x3
    #pragma unroll 3
    for (int j = 0; j < CZ - 1; ++j) {
        ABCp c = plane_abc(Pp, y0ok, true, y2ok, cx, TWO2);
        acc += emit4(m2, m1, c, TWO2, EPS2);
        m2 = m1; m1 = c;
        Pp += PLANE;
    }
    // final plane z = zstart+CZ (may be out of volume); emits z = zstart+CZ-1
    {
        const bool zv = (zstart + CZ < DD);
        ABCp c = plane_abc(Pp, zv && y0ok, zv, zv && y2ok, cx, TWO2);
        acc += emit4(m2, m1, c, TWO2, EPS2);
    }

    // ---------- block reduction (deterministic) ----------
    __shared__ float wsum[NTHREADS / 32];
    __shared__ int lastFlag;
    const int tid  = ty * BX + tx;
    const int wid  = tid >> 5;
    const int lane = tid & 31;

    float v = acc;
    #pragma unroll
    for (int o = 16; o > 0; o >>= 1)
        v += __shfl_down_sync(FULL, v, o);
    if (lane == 0) wsum[wid] = v;
    __syncthreads();

    if (tid == 0) {
        float s = 0.f;
        #pragma unroll
        for (int w = 0; w < NTHREADS / 32; ++w) s += wsum[w];
        g_partial[blockIdx.z * GY + blockIdx.y] = s;
        __threadfence();
        unsigned d = atomicAdd(&g_done, 1u);
        lastFlag = (d == NBLK - 1);
    }
    __syncthreads();

    // ---------- last block folds all partials (fixed order -> deterministic) ----------
    if (lastFlag) {
        const volatile float* gp = g_partial;
        float s = 0.f;
        for (int i = tid; i < NBLK; i += NTHREADS)
            s += gp[i];
        #pragma unroll
        for (int o = 16; o > 0; o >>= 1)
            s += __shfl_down_sync(FULL, s, o);
        if (lane == 0) wsum[wid] = s;
        __syncthreads();
        if (tid == 0) {
            float tot = 0.f;
            #pragma unroll
            for (int w = 0; w < NTHREADS / 32; ++w) tot += wsum[w];
            out[0] = tot * (float)(0.5 / NVOX);   // 0.5: both lanes accumulated
            g_done = 0;    // reset for next graph replay
        }
    }
}

extern "C" void kernel_launch(void* const* d_in, const int* in_sizes, int n_in,
                              void* d_out, int out_size) {
    const float* pred = (const float*)d_in[0];
    const float* targ = (const float*)d_in[1];
    dim3 blk(BX, BY, 1);
    dim3 grd(1, GY, NCID);
    sobel_loss_fused<<<grd, blk>>>(pred, targ, (float*)d_out);
}